// round 16
// baseline (speedup 1.0000x reference)
#include <cuda_runtime.h>
#include <math.h>
#include <stdint.h>

// ---------------------------------------------------------------------------
// Problem constants
// ---------------------------------------------------------------------------
#define DIMD  1024
#define BATCH 8
#define SEQ   4096
#define MTOT  (BATCH * SEQ)
#define NSCAN 128
#define EPER  (DIMD / NSCAN)   // 8

// ---------------------------------------------------------------------------
// Scratch (device-global; no allocation allowed)
// ---------------------------------------------------------------------------
__device__ float    g_inp   [(size_t)MTOT * DIMD];
__device__ float    g_gate  [(size_t)MTOT * DIMD];
__device__ float    g_u     [(size_t)MTOT * DIMD];
__device__ float    g_states[(size_t)MTOT * DIMD];
// pair-packed state: g_sp2[buf][b*512 + p] = { hi-bf16x2(dims 2p,2p+1),
//                                              lo-bf16x2(dims 2p,2p+1) }
__device__ __align__(16) uint2 g_sp2[2][BATCH * 512];
__device__ unsigned g_counter;

// ---------------------------------------------------------------------------
// Helpers
// ---------------------------------------------------------------------------
__device__ __forceinline__ uint32_t smem_u32(const void* p) {
    uint32_t a;
    asm("{ .reg .u64 t; cvta.to.shared.u64 t, %1; cvt.u32.u64 %0, t; }" : "=r"(a) : "l"(p));
    return a;
}

#define LDSM4(r, addr)                                                        \
    asm volatile("ldmatrix.sync.aligned.m8n8.x4.shared.b16 {%0,%1,%2,%3}, [%4];" \
        : "=r"((r)[0]), "=r"((r)[1]), "=r"((r)[2]), "=r"((r)[3]) : "r"(addr))

#define LDSM2(r0, r1, addr)                                                   \
    asm volatile("ldmatrix.sync.aligned.m8n8.x2.shared.b16 {%0,%1}, [%2];"    \
        : "=r"(r0), "=r"(r1) : "r"(addr))

#define MMA16816(d, a, b)                                                     \
    asm volatile("mma.sync.aligned.m16n8k16.row.col.f32.bf16.bf16.f32 "       \
        "{%0,%1,%2,%3}, {%4,%5,%6,%7}, {%8,%9}, {%0,%1,%2,%3};"               \
        : "+f"((d)[0]), "+f"((d)[1]), "+f"((d)[2]), "+f"((d)[3])              \
        : "r"((a)[0]), "r"((a)[1]), "r"((a)[2]), "r"((a)[3]),                 \
          "r"((b)[0]), "r"((b)[1]))

// A rows 8-15 structurally zero -> a1 = a3 = 0 (validated R7/R8/R15)
#define MMAZ(d, a0v, a2v, b)                                                  \
    asm volatile("mma.sync.aligned.m16n8k16.row.col.f32.bf16.bf16.f32 "       \
        "{%0,%1,%2,%3}, {%4,%5,%6,%7}, {%8,%9}, {%0,%1,%2,%3};"               \
        : "+f"((d)[0]), "+f"((d)[1]), "+f"((d)[2]), "+f"((d)[3])              \
        : "r"(a0v), "r"(0u), "r"(a2v), "r"(0u),                               \
          "r"((b)[0]), "r"((b)[1]))

__device__ __forceinline__ uint32_t hipack(float x0, float x1) {
    return __byte_perm(__float_as_uint(x0), __float_as_uint(x1), 0x7632);
}
__device__ __forceinline__ uint32_t lopack(float x0, float x1) {
    float t0 = __uint_as_float(__float_as_uint(x0) & 0xFFFF0000u);
    float t1 = __uint_as_float(__float_as_uint(x1) & 0xFFFF0000u);
    float r0 = x0 - t0, r1 = x1 - t1;
    uint32_t d;
    asm("cvt.rn.bf16x2.f32 %0, %1, %2;" : "=r"(d) : "f"(r1), "f"(r0));
    return d;
}
__device__ __forceinline__ void split8(const float4& a, const float4& b,
                                       uint4& hi, uint4& lo) {
    hi.x = hipack(a.x, a.y); hi.y = hipack(a.z, a.w);
    hi.z = hipack(b.x, b.y); hi.w = hipack(b.z, b.w);
    lo.x = lopack(a.x, a.y); lo.y = lopack(a.z, a.w);
    lo.z = lopack(b.x, b.y); lo.w = lopack(b.z, b.w);
}

__device__ __forceinline__ uint32_t swz(int row, int half) {
    return (uint32_t)(row * 32 + ((half ^ ((row >> 2) & 1)) << 4));
}

__device__ __forceinline__ uint4 ldcg4(const uint4* p) {
    uint4 v;
    asm volatile("ld.global.cg.v4.u32 {%0,%1,%2,%3}, [%4];"
                 : "=r"(v.x), "=r"(v.y), "=r"(v.z), "=r"(v.w) : "l"(p));
    return v;
}
__device__ __forceinline__ void red_release_add1(unsigned* p) {
    asm volatile("red.release.gpu.global.add.u32 [%0], 1;" :: "l"(p) : "memory");
}
__device__ __forceinline__ unsigned ld_acquire(const unsigned* p) {
    unsigned v;
    asm volatile("ld.acquire.gpu.global.u32 %0, [%1];" : "=r"(v) : "l"(p) : "memory");
    return v;
}
__device__ __forceinline__ void stcg2(uint2* p, uint2 v) {
    asm volatile("st.global.cg.v2.u32 [%0], {%1,%2};" :: "l"(p), "r"(v.x), "r"(v.y) : "memory");
}

// ---------------------------------------------------------------------------
// Init kernel
// ---------------------------------------------------------------------------
__global__ void init_kernel() {
    int t = blockIdx.x * blockDim.x + threadIdx.x;
    if (t < BATCH * 512) {
        g_sp2[0][t] = make_uint2(0u, 0u);
        g_sp2[1][t] = make_uint2(0u, 0u);
    }
    if (t == 0) g_counter = 0u;
}

// ---------------------------------------------------------------------------
// bf16 3x-split tensor-core GEMM (R12/R14/R15 version, measured 597us each)
// ---------------------------------------------------------------------------
#define GK 1024
#define GN 1024
#define NCHUNK (GK / 16)

template <int EPI>
__global__ __launch_bounds__(256, 2)
void gemm_mma(const float* __restrict__ X, const float* __restrict__ W,
              const float* __restrict__ bias, float* __restrict__ C)
{
    __shared__ __align__(1024) unsigned char sm[2][4][4096];

    const int tid = threadIdx.x;
    const int wid = tid >> 5, l = tid & 31;
    const int bm = blockIdx.y * 128, bn = blockIdx.x * 128;
    const int wm = wid & 1, wn = wid >> 1;

    const int srow = tid >> 1, shalf = tid & 1;
    const float* Xp = X + (size_t)(bm + srow) * GK + shalf * 8;
    const float* Wp = W + (size_t)(bn + srow) * GK + shalf * 8;
    const uint32_t soff = swz(srow, shalf);

    const int lrow = l & 15, lhalf = l >> 4;
    uint32_t offA[4], offB[2];
#pragma unroll
    for (int mi = 0; mi < 4; mi++) offA[mi] = swz(wm * 64 + mi * 16 + lrow, lhalf);
#pragma unroll
    for (int gi = 0; gi < 2; gi++) offB[gi] = swz(wn * 32 + gi * 16 + lrow, lhalf);

    const uint32_t smbase = smem_u32(&sm[0][0][0]);

    float acc[4][4][4];
#pragma unroll
    for (int mi = 0; mi < 4; mi++)
#pragma unroll
        for (int ni = 0; ni < 4; ni++)
#pragma unroll
            for (int r = 0; r < 4; r++) acc[mi][ni][r] = 0.f;

    {
        float4 a0 = *(const float4*)(Xp + 0), a1 = *(const float4*)(Xp + 4);
        float4 b0 = *(const float4*)(Wp + 0), b1 = *(const float4*)(Wp + 4);
        uint4 hiA, loA, hiB, loB;
        split8(a0, a1, hiA, loA);
        split8(b0, b1, hiB, loB);
        *(uint4*)(&sm[0][0][soff]) = hiA;
        *(uint4*)(&sm[0][1][soff]) = loA;
        *(uint4*)(&sm[0][2][soff]) = hiB;
        *(uint4*)(&sm[0][3][soff]) = loB;
    }
    __syncthreads();

    for (int c = 0; c < NCHUNK; c++) {
        float4 na0, na1, nb0, nb1;
        if (c + 1 < NCHUNK) {
            const int kc = (c + 1) * 16;
            na0 = *(const float4*)(Xp + kc);     na1 = *(const float4*)(Xp + kc + 4);
            nb0 = *(const float4*)(Wp + kc);     nb1 = *(const float4*)(Wp + kc + 4);
        }

        const uint32_t sb = smbase + (uint32_t)(c & 1) * 16384u;

        uint32_t ah[4][4], al[4][4];
#pragma unroll
        for (int mi = 0; mi < 4; mi++) {
            LDSM4(ah[mi], sb + 0 * 4096u + offA[mi]);
            LDSM4(al[mi], sb + 1 * 4096u + offA[mi]);
        }
        uint32_t bh[4][2], bl[4][2];
#pragma unroll
        for (int gi = 0; gi < 2; gi++) {
            uint32_t t[4];
            LDSM4(t, sb + 2 * 4096u + offB[gi]);
            bh[2 * gi + 0][0] = t[0]; bh[2 * gi + 0][1] = t[2];
            bh[2 * gi + 1][0] = t[1]; bh[2 * gi + 1][1] = t[3];
            LDSM4(t, sb + 3 * 4096u + offB[gi]);
            bl[2 * gi + 0][0] = t[0]; bl[2 * gi + 0][1] = t[2];
            bl[2 * gi + 1][0] = t[1]; bl[2 * gi + 1][1] = t[3];
        }

#pragma unroll
        for (int mi = 0; mi < 4; mi++)
#pragma unroll
            for (int ni = 0; ni < 4; ni++)
                MMA16816(acc[mi][ni], ah[mi], bh[ni]);
#pragma unroll
        for (int mi = 0; mi < 4; mi++)
#pragma unroll
            for (int ni = 0; ni < 4; ni++)
                MMA16816(acc[mi][ni], ah[mi], bl[ni]);
#pragma unroll
        for (int mi = 0; mi < 4; mi++)
#pragma unroll
            for (int ni = 0; ni < 4; ni++)
                MMA16816(acc[mi][ni], al[mi], bh[ni]);

        if (c + 1 < NCHUNK) {
            __syncthreads();
            const int s = (c + 1) & 1;
            uint4 hiA, loA, hiB, loB;
            split8(na0, na1, hiA, loA);
            split8(nb0, nb1, hiB, loB);
            *(uint4*)(&sm[s][0][soff]) = hiA;
            *(uint4*)(&sm[s][1][soff]) = loA;
            *(uint4*)(&sm[s][2][soff]) = hiB;
            *(uint4*)(&sm[s][3][soff]) = loB;
            __syncthreads();
        }
    }

    const int erow  = bm + wm * 64 + (l >> 2);
    const int ecol0 = bn + wn * 32 + 2 * (l & 3);

    float2 bv[4];
#pragma unroll
    for (int ni = 0; ni < 4; ni++) {
        if (bias) {
            bv[ni].x = bias[ecol0 + ni * 8];
            bv[ni].y = bias[ecol0 + ni * 8 + 1];
        } else {
            bv[ni].x = 0.f; bv[ni].y = 0.f;
        }
    }

#pragma unroll
    for (int mi = 0; mi < 4; mi++) {
#pragma unroll
        for (int ni = 0; ni < 4; ni++) {
            const int r = erow + mi * 16;
            float2 v0, v1;
            v0.x = acc[mi][ni][0] + bv[ni].x;
            v0.y = acc[mi][ni][1] + bv[ni].y;
            v1.x = acc[mi][ni][2] + bv[ni].x;
            v1.y = acc[mi][ni][3] + bv[ni].y;
            if (EPI == 1) {
                v0.x = 1.f / (1.f + expf(-v0.x));
                v0.y = 1.f / (1.f + expf(-v0.y));
                v1.x = 1.f / (1.f + expf(-v1.x));
                v1.y = 1.f / (1.f + expf(-v1.y));
            }
            *(float2*)(C + (size_t)r * GN + ecol0 + ni * 8)       = v0;
            *(float2*)(C + (size_t)(r + 8) * GN + ecol0 + ni * 8) = v1;
        }
    }
}

// ---------------------------------------------------------------------------
// Scan: R15 structure (8-row tiles, LDSM2+MMAZ, warp-local staging, early
// release) with PAIR-PACKED state: staging is LDG.128 -> STS.64 with ZERO
// unpack ALU, and g_states store moved after the release.
// ---------------------------------------------------------------------------
#define SCAN_SMEM (2 * 16384 + 2048)   // SH 8x2048, SL 8x2048, RED [8][64]

__global__ __launch_bounds__(256, 1)
void scan_mma(const float* __restrict__ A)
{
    extern __shared__ unsigned char sms[];
    unsigned char* SH = sms;                    // 8 rows (batch) x 2048 B
    unsigned char* SL = sms + 16384;
    float* RED        = (float*)(sms + 32768);  // [8][64]

    const int tid = threadIdx.x;
    const int w   = tid >> 5;
    const int l   = tid & 31;
    const int eBase = blockIdx.x * EPER;

    const uint32_t shb = smem_u32(SH);
    const uint32_t slb = smem_u32(SL);

    // --- stationary B fragments: B[k][n] = Amat[eBase+n][k], pre-split hi/lo
    uint32_t uH[8][2], uL[8][2];
    {
        const int e_row = eBase + (l >> 2);
#pragma unroll
        for (int j = 0; j < 8; j++) {
#pragma unroll
            for (int r = 0; r < 2; r++) {
                int k = 128 * w + 16 * j + 2 * (l & 3) + 8 * r;
                float2 av = *(const float2*)(A + (size_t)e_row * DIMD + k);
                uH[j][r] = hipack(av.x, av.y);
                uL[j][r] = lopack(av.x, av.y);
            }
        }
    }

    // --- ldmatrix.x2 lane geometry (8-row tiles; R15 verified)
    const int lr  = l & 7;
    const int sel = (l >> 3) & 1;
    const uint32_t lrow_off = (uint32_t)(lr * 2048);
    const uint32_t lxr      = (uint32_t)(lr << 4);
    const uint32_t cbase    = (uint32_t)(256 * w);

    // --- epilogue mapping (threads 0..63 own one (b,e) output)
    const int b_o = tid >> 3;
    const int e_o = tid & 7;

    float u_r = 0.f, g_r = 0.f, i_r = 0.f;
    if (tid < 64) {
        size_t idx0 = (size_t)b_o * SEQ * DIMD + (size_t)(eBase + e_o);
        u_r = g_u[idx0]; g_r = g_gate[idx0]; i_r = g_inp[idx0];
    }

    // pair-pack destination (even e_o threads): p = (eBase + e_o) / 2
    const int pwr = b_o * 512 + ((eBase + e_o) >> 1);

    // --- warp-local staging geometry: warp w covers e-pairs
    //     [64w + 2l, 64w + 2l + 2) of EVERY batch row (= dims 128w+4l..4l+3)
    const uint32_t scolbase = 256u * (uint32_t)w + 8u * (uint32_t)l;

    __syncthreads();

    for (int t = 0; t < SEQ; t++) {
        // 1) load pair-packed state: uint4 = {hi(p0), lo(p0), hi(p1), lo(p1)}
        const uint2* sp = g_sp2[t & 1];
        uint4 p[8];
#pragma unroll
        for (int b = 0; b < 8; b++)
            p[b] = ldcg4((const uint4*)(sp + (uint32_t)b * 512 + 64u * w + 2u * l));

        // 2) stage into this warp's SMEM window -- zero ALU, reg selection only
#pragma unroll
        for (int b = 0; b < 8; b++) {
            uint32_t cb = scolbase ^ ((uint32_t)b << 4);
            *(uint2*)(SH + b * 2048 + cb) = make_uint2(p[b].x, p[b].z);
            *(uint2*)(SL + b * 2048 + cb) = make_uint2(p[b].y, p[b].w);
        }
        __syncwarp();   // warp-local staging complete (no CTA barrier)

        // 3) 8 chunks x 3 split MMAs, 8-row fragments (LDSM2 + MMAZ)
        float acc0[4] = {0.f, 0.f, 0.f, 0.f};
        float acc1[4] = {0.f, 0.f, 0.f, 0.f};
#pragma unroll
        for (int j = 0; j < 8; j++) {
            uint32_t cb = lrow_off + (((cbase + 32u * j + 16u * sel)) ^ lxr);
            uint32_t h0, h1, s0, s1;
            LDSM2(h0, h1, shb + cb);
            LDSM2(s0, s1, slb + cb);
            float* acc = (j & 1) ? acc1 : acc0;
            MMAZ(acc, h0, h1, uH[j]);
            MMAZ(acc, h0, h1, uL[j]);
            MMAZ(acc, s0, s1, uH[j]);
        }
        float c0 = acc0[0] + acc1[0];
        float c1 = acc0[1] + acc1[1];

        // 4) cross-warp reduce partials
        *(float2*)&RED[w * 64 + (l >> 2) * 8 + 2 * (l & 3)] = make_float2(c0, c1);
        __syncthreads();   // S2: partials visible

        // 5) epilogue -> pair-pack state -> early release -> deferred extras
        if (tid < 64) {
            float y = 0.f;
#pragma unroll
            for (int ww = 0; ww < 8; ww++) y += RED[ww * 64 + tid];

            float sv = tanhf(y + u_r);
            sv = g_r * sv + (1.f - g_r) * i_r;

            // pair up: thread with even e_o packs (sv, neighbor sv)
            float svn = __shfl_down_sync(0xffffffffu, sv, 1);
            if ((tid & 1) == 0) {
                uint2 pw;
                pw.x = hipack(sv, svn);
                pw.y = lopack(sv, svn);
                stcg2(&g_sp2[(t + 1) & 1][pwr], pw);
            }

            // order state stores across the 64 epi threads, then release NOW
            asm volatile("bar.sync 3, 64;" ::: "memory");
            if (tid == 0) {
                red_release_add1(&g_counter);
                const unsigned target = (unsigned)NSCAN * (unsigned)(t + 1);
                while (ld_acquire(&g_counter) < target) { }
            }

            // off-chain work AFTER the release
            g_states[((size_t)b_o * SEQ + t) * DIMD + eBase + e_o] = sv;
            if (t + 1 < SEQ) {
                size_t idx = ((size_t)b_o * SEQ + (t + 1)) * DIMD + (eBase + e_o);
                u_r = g_u[idx]; g_r = g_gate[idx]; i_r = g_inp[idx];
            }
        }
        __syncthreads();   // S3 (merged): poll done -> state(t+1) readable
    }
}

// ---------------------------------------------------------------------------
// kernel_launch
// ---------------------------------------------------------------------------
extern "C" void kernel_launch(void* const* d_in, const int* in_sizes, int n_in,
                              void* d_out, int out_size)
{
    (void)in_sizes; (void)n_in; (void)out_size;

    const float* x      = (const float*)d_in[0];
    const float* A      = (const float*)d_in[1];
    const float* Bmat   = (const float*)d_in[2];
    const float* W_in   = (const float*)d_in[3];
    const float* b_in   = (const float*)d_in[4];
    const float* W_gate = (const float*)d_in[5];
    const float* b_gate = (const float*)d_in[6];
    const float* W_out  = (const float*)d_in[7];
    const float* b_out  = (const float*)d_in[8];
    float* out          = (float*)d_out;

    void *p_inp, *p_gate, *p_u, *p_states;
    cudaGetSymbolAddress(&p_inp,    g_inp);
    cudaGetSymbolAddress(&p_gate,   g_gate);
    cudaGetSymbolAddress(&p_u,      g_u);
    cudaGetSymbolAddress(&p_states, g_states);

    float* inp    = (float*)p_inp;
    float* gate   = (float*)p_gate;
    float* u      = (float*)p_u;
    float* states = (float*)p_states;

    cudaFuncSetAttribute(scan_mma, cudaFuncAttributeMaxDynamicSharedMemorySize, SCAN_SMEM);

    init_kernel<<<(BATCH * 512 + 255) / 256, 256>>>();

    dim3 gg(DIMD / 128, MTOT / 128);   // (8, 256)

    gemm_mma<0><<<gg, 256>>>(x, W_in, b_in, inp);
    gemm_mma<1><<<gg, 256>>>(inp, W_gate, b_gate, gate);
    gemm_mma<0><<<gg, 256>>>(inp, Bmat, nullptr, u);
    scan_mma<<<NSCAN, 256, SCAN_SMEM>>>(A);
    gemm_mma<0><<<gg, 256>>>(states, W_out, b_out, out);
}